// round 10
// baseline (speedup 1.0000x reference)
#include <cuda_runtime.h>

#define IN_DIM  1024
#define OUT_DIM 512
#define B_DIM   128
#define OPB     8                    // o's per block = warps per block
#define ICH     64                   // i-chunk per block
#define NSPLIT  (IN_DIM / ICH)       // 16
#define NOUT    (B_DIM * OUT_DIM)    // 65536
#define NGRP    4                    // reduce stage-1 groups (4 splits each)
#define TAU_W   0.045f               // |w|<tau -> |z|<~0.3 (deg-3 poly valid)

// Partial sums: [split][o][b]  (16 * 512 * 128 * 4B = 4 MB)
__device__ float g_part[NSPLIT * NOUT];
// Stage-1 partials: [group][o*128+b]  (1 MB)
__device__ float g_mid[NGRP * NOUT];

__device__ __forceinline__ float tanh_approx(float x) {
    float y;
    asm("tanh.approx.f32 %0, %1;" : "=f"(y) : "f"(x));
    return y;
}
__device__ __forceinline__ float rcp_approx(float x) {
    float y;
    asm("rcp.approx.f32 %0, %1;" : "=f"(y) : "f"(x));
    return y;
}

// Fused kernel. Block = 8 warps; warp w owns output column o0+w for ALL 128
// batches over a 64-wide i-chunk.
//   1) warp computes its own 64 W_eff values (2/lane)
//   2) partitions the 64 i's by |w| < TAU_W (ballot + prefix, deterministic)
//   3) paired loop: one poly-i (FMA pipe) + one mufu-i (MUFU pipe) per
//      iteration so both pipes run concurrently; drain loop for the surplus.
__global__ __launch_bounds__(256, 5)
void fbn_fused_kernel(const float* __restrict__ x,
                      const float* __restrict__ W,
                      const float* __restrict__ theta) {
    __shared__ float xs[ICH][B_DIM];      // x transposed [i][b], 32 KB
    __shared__ float wp[OPB][ICH];        // permuted w per warp, 2 KB
    __shared__ int   pidx[OPB][ICH];      // permuted i per warp, 2 KB

    const int tid  = threadIdx.x;
    const int wid  = tid >> 5;
    const int lane = tid & 31;
    const int o0   = blockIdx.x * OPB;
    const int c0   = blockIdx.y * ICH;

    // ---- 1) W_eff for this warp's o: i = lane and lane+32 ----
    float w0, w1;
    {
        const float4* t4 = reinterpret_cast<const float4*>(theta);
        int g0 = (o0 + wid) * IN_DIM + c0 + lane;
        int g1 = g0 + 32;
        float4 ta = t4[g0];
        float4 tb = t4[g1];
        float Wa = W[g0];
        float Wb = W[g1];
        {
            float a = __expf(ta.x), b = __expf(ta.y), c = __expf(ta.z), d = __expf(ta.w);
            float inv = rcp_approx(a + b + c + d);
            w0 = (b * Wa + c * tanh_approx(Wa) + d * __sinf(Wa)) * inv;
        }
        {
            float a = __expf(tb.x), b = __expf(tb.y), c = __expf(tb.z), d = __expf(tb.w);
            float inv = rcp_approx(a + b + c + d);
            w1 = (b * Wb + c * tanh_approx(Wb) + d * __sinf(Wb)) * inv;
        }
    }

    // ---- 2) partition the warp's 64 i's: poly [0,ns), mufu [ns,64) ----
    int ns;
    {
        bool s0 = fabsf(w0) < TAU_W;
        bool s1 = fabsf(w1) < TAU_W;
        unsigned m0 = __ballot_sync(0xffffffffu, s0);
        unsigned m1 = __ballot_sync(0xffffffffu, s1);
        int n0 = __popc(m0);
        ns = n0 + __popc(m1);
        unsigned lt = (1u << lane) - 1u;
        int p0 = s0 ? __popc(m0 & lt)
                    : ns + __popc(~m0 & lt);
        int p1 = s1 ? n0 + __popc(m1 & lt)
                    : ns + __popc(~m0) + __popc(~m1 & lt);
        wp[wid][p0] = w0;  pidx[wid][p0] = lane;
        wp[wid][p1] = w1;  pidx[wid][p1] = lane + 32;
    }

    // ---- x staging: xs[i][b], coalesced LDG.128, conflict-free STS ----
    {
        const float4* x4 = reinterpret_cast<const float4*>(x);
        #pragma unroll
        for (int k = 0; k < 4; k++) {
            int f = tid + k * 256;          // 0..1023
            int b = f & 127, i8 = f >> 7;   // i8 = 0..7
            float4 v0 = x4[b * (IN_DIM / 4) + (c0 >> 2) + i8 * 2];
            float4 v1 = x4[b * (IN_DIM / 4) + (c0 >> 2) + i8 * 2 + 1];
            xs[i8 * 8 + 0][b] = v0.x; xs[i8 * 8 + 1][b] = v0.y;
            xs[i8 * 8 + 2][b] = v0.z; xs[i8 * 8 + 3][b] = v0.w;
            xs[i8 * 8 + 4][b] = v1.x; xs[i8 * 8 + 5][b] = v1.y;
            xs[i8 * 8 + 6][b] = v1.z; xs[i8 * 8 + 7][b] = v1.w;
        }
    }
    __syncthreads();

    // ---- 3) compute: lane owns batches 4*lane .. 4*lane+3 ----
    const int bb = lane * 4;
    const float C3 = -0.33333334f;
    float ap0 = 0.f, ap1 = 0.f, ap2 = 0.f, ap3 = 0.f;   // poly accumulators
    float am0 = 0.f, am1 = 0.f, am2 = 0.f, am3 = 0.f;   // mufu accumulators

    const int nm = ICH - ns;
    const int npair = ns < nm ? ns : nm;

    // Paired loop: 1 mufu-i + 1 poly-i -> MUFU and FMA pipes run together.
    for (int k = 0; k < npair; k++) {
        float wmv = wp[wid][ns + k];
        int   im  = pidx[wid][ns + k];
        float wpv = wp[wid][k];
        int   ip  = pidx[wid][k];
        float4 xm = *reinterpret_cast<const float4*>(&xs[im][bb]);
        float4 xp = *reinterpret_cast<const float4*>(&xs[ip][bb]);
        // mufu elems (issue MUFU early, long latency)
        float t0 = tanh_approx(xm.x * wmv);
        float t1 = tanh_approx(xm.y * wmv);
        float t2 = tanh_approx(xm.z * wmv);
        float t3 = tanh_approx(xm.w * wmv);
        // poly elems: tanh(z) ~= z * (1 + C3*z^2)
        float z0 = xp.x * wpv, z1 = xp.y * wpv, z2 = xp.z * wpv, z3 = xp.w * wpv;
        float q0 = fmaf(z0 * z0, C3, 1.0f);
        float q1 = fmaf(z1 * z1, C3, 1.0f);
        float q2 = fmaf(z2 * z2, C3, 1.0f);
        float q3 = fmaf(z3 * z3, C3, 1.0f);
        ap0 = fmaf(z0, q0, ap0);
        ap1 = fmaf(z1, q1, ap1);
        ap2 = fmaf(z2, q2, ap2);
        ap3 = fmaf(z3, q3, ap3);
        am0 += t0; am1 += t1; am2 += t2; am3 += t3;
    }
    // Drain poly surplus
    for (int k = npair; k < ns; k++) {
        float wpv = wp[wid][k];
        int   ip  = pidx[wid][k];
        float4 xp = *reinterpret_cast<const float4*>(&xs[ip][bb]);
        float z0 = xp.x * wpv, z1 = xp.y * wpv, z2 = xp.z * wpv, z3 = xp.w * wpv;
        float q0 = fmaf(z0 * z0, C3, 1.0f);
        float q1 = fmaf(z1 * z1, C3, 1.0f);
        float q2 = fmaf(z2 * z2, C3, 1.0f);
        float q3 = fmaf(z3 * z3, C3, 1.0f);
        ap0 = fmaf(z0, q0, ap0);
        ap1 = fmaf(z1, q1, ap1);
        ap2 = fmaf(z2, q2, ap2);
        ap3 = fmaf(z3, q3, ap3);
    }
    // Drain mufu surplus
    for (int k = ns + npair; k < ICH; k++) {
        float wmv = wp[wid][k];
        int   im  = pidx[wid][k];
        float4 xm = *reinterpret_cast<const float4*>(&xs[im][bb]);
        am0 += tanh_approx(xm.x * wmv);
        am1 += tanh_approx(xm.y * wmv);
        am2 += tanh_approx(xm.z * wmv);
        am3 += tanh_approx(xm.w * wmv);
    }

    float4 res = make_float4(ap0 + am0, ap1 + am1, ap2 + am2, ap3 + am3);
    // g_part[split][o][b]: lanes -> consecutive b, STG.128 coalesced
    reinterpret_cast<float4*>(g_part)[
        (blockIdx.y * NOUT + (o0 + wid) * B_DIM + bb) >> 2] = res;
}

// Reduce stage 1: sum 4 splits per thread; 256K threads hide L2 latency.
__global__ __launch_bounds__(256)
void reduce1_kernel() {
    int t = blockIdx.x * blockDim.x + threadIdx.x;    // 0 .. 4*NOUT-1
    int idx = t & (NOUT - 1);
    int g = t >> 16;
    const float* p = g_part + g * 4 * NOUT + idx;
    float v0 = p[0 * NOUT], v1 = p[1 * NOUT], v2 = p[2 * NOUT], v3 = p[3 * NOUT];
    g_mid[g * NOUT + idx] = (v0 + v1) + (v2 + v3);
}

// Reduce stage 2: out[b][o] = bias[o] + sum of 4 group sums.
__global__ __launch_bounds__(256)
void reduce2_kernel(const float* __restrict__ bias,
                    float* __restrict__ out) {
    int idx = blockIdx.x * blockDim.x + threadIdx.x;   // idx = o*128 + b
    float a = g_mid[0 * NOUT + idx];
    float b = g_mid[1 * NOUT + idx];
    float c = g_mid[2 * NOUT + idx];
    float d = g_mid[3 * NOUT + idx];
    int o = idx >> 7, bi = idx & 127;
    out[bi * OUT_DIM + o] = bias[o] + ((a + b) + (c + d));
}

extern "C" void kernel_launch(void* const* d_in, const int* in_sizes, int n_in,
                              void* d_out, int out_size) {
    const float* x     = (const float*)d_in[0];   // (128, 1024)
    const float* W     = (const float*)d_in[1];   // (512, 1024)
    const float* bias  = (const float*)d_in[2];   // (512,)
    const float* theta = (const float*)d_in[3];   // (512, 1024, 4)
    float* out = (float*)d_out;                   // (128, 512)

    (void)in_sizes; (void)n_in; (void)out_size;

    dim3 grid(OUT_DIM / OPB, NSPLIT);   // (64, 16) = 1024 blocks
    fbn_fused_kernel<<<grid, 256>>>(x, W, theta);

    reduce1_kernel<<<(NGRP * NOUT) / 256, 256>>>();
    reduce2_kernel<<<NOUT / 256, 256>>>(bias, out);
}

// round 11
// speedup vs baseline: 1.0010x; 1.0010x over previous
#include <cuda_runtime.h>

#define IN_DIM  1024
#define OUT_DIM 512
#define B_DIM   128
#define OPB     8                    // o's per block = warps per block
#define ICH     64                   // i-chunk per block
#define NSPLIT  (IN_DIM / ICH)       // 16
#define NOUT    (B_DIM * OUT_DIM)    // 65536
#define NGRP    4                    // reduce stage-1 groups (4 splits each)
#define TAU_W   0.045f               // |w|<tau -> |z|<~0.25 (deg-3 poly valid)

// Partial sums: [split][o][b]  (16 * 512 * 128 * 4B = 4 MB)
__device__ float g_part[NSPLIT * NOUT];
// Stage-1 partials: [group][o*128+b]  (1 MB)
__device__ float g_mid[NGRP * NOUT];

__device__ __forceinline__ float tanh_approx(float x) {
    float y;
    asm("tanh.approx.f32 %0, %1;" : "=f"(y) : "f"(x));
    return y;
}
__device__ __forceinline__ float rcp_approx(float x) {
    float y;
    asm("rcp.approx.f32 %0, %1;" : "=f"(y) : "f"(x));
    return y;
}

// Fused kernel. Block = 8 warps; warp w owns output column o0+w for ALL 128
// batches over a 64-wide i-chunk.
//   1) warp computes its own 64 W_eff values (2/lane)
//   2) partitions the 64 i's by |w| < TAU_W into a packed (w, x-row-offset)
//      array: poly class [0,ns), mufu class [ns,64)  -- w is warp-uniform,
//      so partition is divergence-free and deterministic
//   3) two tight uniform loops: poly (FMA pipe) then mufu (MUFU pipe).
//      Pipe overlap happens ACROSS warps (~32 resident warps per SM mix
//      phases), with only 2 LDS per warp-i.
__global__ __launch_bounds__(256)
void fbn_fused_kernel(const float* __restrict__ x,
                      const float* __restrict__ W,
                      const float* __restrict__ theta) {
    __shared__ float  xs[ICH][B_DIM];     // x transposed [i][b], 32 KB
    __shared__ float2 wpk[OPB][ICH];      // packed {w, bitcast(i*B_DIM)}, 4 KB

    const int tid  = threadIdx.x;
    const int wid  = tid >> 5;
    const int lane = tid & 31;
    const int o0   = blockIdx.x * OPB;
    const int c0   = blockIdx.y * ICH;

    // ---- 1) W_eff for this warp's o: i = lane and lane+32 ----
    float w0, w1;
    {
        const float4* t4 = reinterpret_cast<const float4*>(theta);
        int g0 = (o0 + wid) * IN_DIM + c0 + lane;
        int g1 = g0 + 32;
        float4 ta = t4[g0];
        float4 tb = t4[g1];
        float Wa = W[g0];
        float Wb = W[g1];
        {
            float a = __expf(ta.x), b = __expf(ta.y), c = __expf(ta.z), d = __expf(ta.w);
            float inv = rcp_approx(a + b + c + d);
            w0 = (b * Wa + c * tanh_approx(Wa) + d * __sinf(Wa)) * inv;
        }
        {
            float a = __expf(tb.x), b = __expf(tb.y), c = __expf(tb.z), d = __expf(tb.w);
            float inv = rcp_approx(a + b + c + d);
            w1 = (b * Wb + c * tanh_approx(Wb) + d * __sinf(Wb)) * inv;
        }
    }

    // ---- 2) partition the warp's 64 i's: poly [0,ns), mufu [ns,64) ----
    int ns;
    {
        bool s0 = fabsf(w0) < TAU_W;
        bool s1 = fabsf(w1) < TAU_W;
        unsigned m0 = __ballot_sync(0xffffffffu, s0);
        unsigned m1 = __ballot_sync(0xffffffffu, s1);
        int n0 = __popc(m0);
        ns = n0 + __popc(m1);
        unsigned lt = (1u << lane) - 1u;
        int p0 = s0 ? __popc(m0 & lt)
                    : ns + __popc(~m0 & lt);
        int p1 = s1 ? n0 + __popc(m1 & lt)
                    : ns + __popc(~m0) + __popc(~m1 & lt);
        wpk[wid][p0] = make_float2(w0, __int_as_float(lane * B_DIM));
        wpk[wid][p1] = make_float2(w1, __int_as_float((lane + 32) * B_DIM));
    }

    // ---- x staging: xs[i][b], conflict-free STS ----
    {
        const float4* x4 = reinterpret_cast<const float4*>(x);
        #pragma unroll
        for (int k = 0; k < 4; k++) {
            int f = tid + k * 256;          // 0..1023
            int b = f & 127, i8 = f >> 7;   // i8 = 0..7
            float4 v0 = x4[b * (IN_DIM / 4) + (c0 >> 2) + i8 * 2];
            float4 v1 = x4[b * (IN_DIM / 4) + (c0 >> 2) + i8 * 2 + 1];
            xs[i8 * 8 + 0][b] = v0.x; xs[i8 * 8 + 1][b] = v0.y;
            xs[i8 * 8 + 2][b] = v0.z; xs[i8 * 8 + 3][b] = v0.w;
            xs[i8 * 8 + 4][b] = v1.x; xs[i8 * 8 + 5][b] = v1.y;
            xs[i8 * 8 + 6][b] = v1.z; xs[i8 * 8 + 7][b] = v1.w;
        }
    }
    __syncthreads();

    // ---- 3) compute: lane owns batches 4*lane .. 4*lane+3 ----
    const float* xbase = &xs[0][lane * 4];
    const float2* wrow = &wpk[wid][0];
    const float C3 = -0.33333334f;
    float ap0 = 0.f, ap1 = 0.f, ap2 = 0.f, ap3 = 0.f;   // poly accumulators
    float am0 = 0.f, am1 = 0.f, am2 = 0.f, am3 = 0.f;   // mufu accumulators

    // Poly loop: tanh(z) ~= z * (1 + C3*z^2)   (FMA pipe)
    #pragma unroll 4
    for (int k = 0; k < ns; k++) {
        float2 wi = wrow[k];
        float w = wi.x;
        float4 xv = *reinterpret_cast<const float4*>(xbase + __float_as_int(wi.y));
        float z0 = xv.x * w, z1 = xv.y * w, z2 = xv.z * w, z3 = xv.w * w;
        float q0 = fmaf(z0 * z0, C3, 1.0f);
        float q1 = fmaf(z1 * z1, C3, 1.0f);
        float q2 = fmaf(z2 * z2, C3, 1.0f);
        float q3 = fmaf(z3 * z3, C3, 1.0f);
        ap0 = fmaf(z0, q0, ap0);
        ap1 = fmaf(z1, q1, ap1);
        ap2 = fmaf(z2, q2, ap2);
        ap3 = fmaf(z3, q3, ap3);
    }
    // Mufu loop: hardware tanh   (MUFU pipe)
    #pragma unroll 4
    for (int k = ns; k < ICH; k++) {
        float2 wi = wrow[k];
        float w = wi.x;
        float4 xv = *reinterpret_cast<const float4*>(xbase + __float_as_int(wi.y));
        am0 += tanh_approx(xv.x * w);
        am1 += tanh_approx(xv.y * w);
        am2 += tanh_approx(xv.z * w);
        am3 += tanh_approx(xv.w * w);
    }

    float4 res = make_float4(ap0 + am0, ap1 + am1, ap2 + am2, ap3 + am3);
    // g_part[split][o][b]: lanes -> consecutive b, STG.128 coalesced
    reinterpret_cast<float4*>(g_part)[
        (blockIdx.y * NOUT + (o0 + wid) * B_DIM + lane * 4) >> 2] = res;
}

// Reduce stage 1: sum 4 splits per thread; 256K threads hide L2 latency.
__global__ __launch_bounds__(256)
void reduce1_kernel() {
    int t = blockIdx.x * blockDim.x + threadIdx.x;    // 0 .. 4*NOUT-1
    int idx = t & (NOUT - 1);
    int g = t >> 16;
    const float* p = g_part + g * 4 * NOUT + idx;
    float v0 = p[0 * NOUT], v1 = p[1 * NOUT], v2 = p[2 * NOUT], v3 = p[3 * NOUT];
    g_mid[g * NOUT + idx] = (v0 + v1) + (v2 + v3);
}

// Reduce stage 2: out[b][o] = bias[o] + sum of 4 group sums.
__global__ __launch_bounds__(256)
void reduce2_kernel(const float* __restrict__ bias,
                    float* __restrict__ out) {
    int idx = blockIdx.x * blockDim.x + threadIdx.x;   // idx = o*128 + b
    float a = g_mid[0 * NOUT + idx];
    float b = g_mid[1 * NOUT + idx];
    float c = g_mid[2 * NOUT + idx];
    float d = g_mid[3 * NOUT + idx];
    int o = idx >> 7, bi = idx & 127;
    out[bi * OUT_DIM + o] = bias[o] + ((a + b) + (c + d));
}

extern "C" void kernel_launch(void* const* d_in, const int* in_sizes, int n_in,
                              void* d_out, int out_size) {
    const float* x     = (const float*)d_in[0];   // (128, 1024)
    const float* W     = (const float*)d_in[1];   // (512, 1024)
    const float* bias  = (const float*)d_in[2];   // (512,)
    const float* theta = (const float*)d_in[3];   // (512, 1024, 4)
    float* out = (float*)d_out;                   // (128, 512)

    (void)in_sizes; (void)n_in; (void)out_size;

    dim3 grid(OUT_DIM / OPB, NSPLIT);   // (64, 16) = 1024 blocks
    fbn_fused_kernel<<<grid, 256>>>(x, W, theta);

    reduce1_kernel<<<(NGRP * NOUT) / 256, 256>>>();
    reduce2_kernel<<<NOUT / 256, 256>>>(bias, out);
}

// round 12
// speedup vs baseline: 1.1331x; 1.1319x over previous
#include <cuda_runtime.h>

#define IN_DIM  1024
#define OUT_DIM 512
#define B_DIM   128
#define OT      16                  // output tile per block
#define ICH     32                  // input chunk per block
#define NSPLIT  (IN_DIM / ICH)      // 32 partials per (b,o)
#define NOUT    (B_DIM * OUT_DIM)   // 65536
#define NGRP    4                   // reduce stage-1 groups (8 splits each)

// Partial sums: [split][b][o]  (32 * 128 * 512 * 4B = 8 MB)
__device__ float g_part[NSPLIT * NOUT];
// Stage-1 partials: [group][b*512+o]  (1 MB)
__device__ float g_mid[NGRP * NOUT];

__device__ __forceinline__ float tanh_approx(float x) {
    float y;
    asm("tanh.approx.f32 %0, %1;" : "=f"(y) : "f"(x));
    return y;
}
__device__ __forceinline__ float rcp_approx(float x) {
    float y;
    asm("rcp.approx.f32 %0, %1;" : "=f"(y) : "f"(x));
    return y;
}

__device__ __forceinline__ float weff_one(float4 t, float w) {
    float a = __expf(t.x), b = __expf(t.y), c = __expf(t.z), d = __expf(t.w);
    float inv = rcp_approx(a + b + c + d);
    return (b * w + c * tanh_approx(w) + d * __sinf(w)) * inv;
}

// Fused kernel (R6 config — measured fastest): each block owns
// (o-tile 16, i-chunk 32, ALL 128 batches).
// 1) computes its 16x32 W_eff tile (each element exactly once, chip-wide)
// 2) stages the 128x32 x tile
// 3) partial[split][b][o] = sum_{i in chunk} tanh(x[b,i] * W_eff[o,i])
__global__ __launch_bounds__(256, 7)
void fbn_fused_kernel(const float* __restrict__ x,
                      const float* __restrict__ W,
                      const float* __restrict__ theta) {
    __shared__ float ws_t[ICH][OT];          // W_eff transposed [i][o], 2 KB
    __shared__ float xs[B_DIM][ICH];         // x tile [b][i], 16 KB

    const int tid = threadIdx.x;
    const int o0 = blockIdx.x * OT;
    const int c0 = blockIdx.y * ICH;

    // ---- W_eff tile: 512 elements, 2 per thread (m = tid, tid+256) ----
    {
        const float4* t4 = reinterpret_cast<const float4*>(theta);
        int m0 = tid, m1 = tid + 256;
        int ol0 = m0 >> 5, il0 = m0 & 31;
        int ol1 = m1 >> 5, il1 = m1 & 31;
        int g0 = (o0 + ol0) * IN_DIM + c0 + il0;
        int g1 = (o0 + ol1) * IN_DIM + c0 + il1;
        float4 ta = t4[g0];
        float4 tb = t4[g1];
        float wa = W[g0];
        float wb = W[g1];
        ws_t[il0][ol0] = weff_one(ta, wa);
        ws_t[il1][ol1] = weff_one(tb, wb);
    }

    // ---- x tile: 128 rows x 8 float4 = 1024 float4, 4 per thread ----
    {
        const float4* xg = reinterpret_cast<const float4*>(x);
        #pragma unroll
        for (int k = 0; k < 4; k++) {
            int f = tid + k * 256;
            int row = f >> 3, col = f & 7;
            float4 v = xg[row * (IN_DIM / 4) + (c0 >> 2) + col];
            *reinterpret_cast<float4*>(&xs[row][col * 4]) = v;
        }
    }
    __syncthreads();

    // ---- compute: thread = (o = tx, batches ty*8 .. ty*8+7) ----
    const int tx = tid & 15;
    const int ty = tid >> 4;
    const float* xrow = &xs[ty * 8][0];

    float acc0 = 0.f, acc1 = 0.f, acc2 = 0.f, acc3 = 0.f;
    float acc4 = 0.f, acc5 = 0.f, acc6 = 0.f, acc7 = 0.f;

    #pragma unroll 8
    for (int i = 0; i < ICH; i++) {
        float w = ws_t[i][tx];
        acc0 += tanh_approx(xrow[0 * ICH + i] * w);
        acc1 += tanh_approx(xrow[1 * ICH + i] * w);
        acc2 += tanh_approx(xrow[2 * ICH + i] * w);
        acc3 += tanh_approx(xrow[3 * ICH + i] * w);
        acc4 += tanh_approx(xrow[4 * ICH + i] * w);
        acc5 += tanh_approx(xrow[5 * ICH + i] * w);
        acc6 += tanh_approx(xrow[6 * ICH + i] * w);
        acc7 += tanh_approx(xrow[7 * ICH + i] * w);
    }

    float* dst = g_part + (blockIdx.y * B_DIM + ty * 8) * OUT_DIM + o0 + tx;
    dst[0 * OUT_DIM] = acc0;
    dst[1 * OUT_DIM] = acc1;
    dst[2 * OUT_DIM] = acc2;
    dst[3 * OUT_DIM] = acc3;
    dst[4 * OUT_DIM] = acc4;
    dst[5 * OUT_DIM] = acc5;
    dst[6 * OUT_DIM] = acc6;
    dst[7 * OUT_DIM] = acc7;
}

// Reduce stage 1 (R8 config — measured fastest): g_mid[g][idx] = sum of
// 8 splits. 256K threads -> ~54 warps/SM; latency hidden by occupancy.
__global__ __launch_bounds__(256)
void reduce1_kernel() {
    int t = blockIdx.x * blockDim.x + threadIdx.x;    // 0 .. 4*NOUT-1
    int idx = t & (NOUT - 1);
    int g = t >> 16;
    const float* p = g_part + g * 8 * NOUT + idx;
    float v0 = p[0 * NOUT], v1 = p[1 * NOUT], v2 = p[2 * NOUT], v3 = p[3 * NOUT];
    float v4 = p[4 * NOUT], v5 = p[5 * NOUT], v6 = p[6 * NOUT], v7 = p[7 * NOUT];
    v0 += v1; v2 += v3; v4 += v5; v6 += v7;
    g_mid[g * NOUT + idx] = (v0 + v2) + (v4 + v6);
}

// Reduce stage 2: out = bias + sum of 4 group sums (1.25 MB traffic).
__global__ __launch_bounds__(256)
void reduce2_kernel(const float* __restrict__ bias,
                    float* __restrict__ out) {
    int idx = blockIdx.x * blockDim.x + threadIdx.x;   // idx = b*512 + o
    float a = g_mid[0 * NOUT + idx];
    float b = g_mid[1 * NOUT + idx];
    float c = g_mid[2 * NOUT + idx];
    float d = g_mid[3 * NOUT + idx];
    out[idx] = bias[idx & (OUT_DIM - 1)] + ((a + b) + (c + d));
}

extern "C" void kernel_launch(void* const* d_in, const int* in_sizes, int n_in,
                              void* d_out, int out_size) {
    const float* x     = (const float*)d_in[0];   // (128, 1024)
    const float* W     = (const float*)d_in[1];   // (512, 1024)
    const float* bias  = (const float*)d_in[2];   // (512,)
    const float* theta = (const float*)d_in[3];   // (512, 1024, 4)
    float* out = (float*)d_out;                   // (128, 512)

    (void)in_sizes; (void)n_in; (void)out_size;

    dim3 grid(OUT_DIM / OT, IN_DIM / ICH);   // (32, 32) = 1024 blocks, 1 wave @ 7/SM
    fbn_fused_kernel<<<grid, 256>>>(x, W, theta);

    reduce1_kernel<<<(NGRP * NOUT) / 256, 256>>>();
    reduce2_kernel<<<NOUT / 256, 256>>>(bias, out);
}